// round 10
// baseline (speedup 1.0000x reference)
#include <cuda_runtime.h>
#include <cuda_fp16.h>
#include <cstdint>

// Problem constants
#define B_   2
#define S_   2048
#define E_   1024
#define H_   16
#define D_   64
#define HD_  1024
#define N_   4096            // B*S
#define SCALE_ 0.125f        // 1/sqrt(64), exact power of two
#define NEG_  -1e9f

// ---------------- scratch (device globals; no allocations allowed) -------
__device__ __half g_qh[(size_t)B_ * H_ * S_ * D_];   // [bh][s][d], pre-scaled
__device__ __half g_kh[(size_t)B_ * H_ * S_ * D_];
__device__ __half g_vh[(size_t)B_ * H_ * S_ * D_];
__device__ __half g_ctxh[(size_t)N_ * HD_];          // [b*S+s][h*D+d]
__device__ __half g_ah3[(size_t)3 * N_ * E_];        // staged Q/K/V inputs (fp16)
__device__ __half g_wth4[(size_t)4 * E_ * HD_];      // staged W^T x4 (fp16)
__device__ __half g_eh[(size_t)B_ * H_ * S_ * S_];   // exp-scores / 16 (fp16)

// ---------------- helpers --------------------------------------------------
__device__ __forceinline__ uint32_t cvta_smem(const void* p) {
    uint32_t a;
    asm("{ .reg .u64 t; cvta.to.shared.u64 t, %1; cvt.u32.u64 %0, t; }"
        : "=r"(a) : "l"(p));
    return a;
}
__device__ __forceinline__ void ldmx4(uint32_t* d, uint32_t a) {
    asm volatile("ldmatrix.sync.aligned.m8n8.x4.shared.b16 {%0,%1,%2,%3}, [%4];"
                 : "=r"(d[0]), "=r"(d[1]), "=r"(d[2]), "=r"(d[3]) : "r"(a));
}
__device__ __forceinline__ void ldmx4t(uint32_t* d, uint32_t a) {
    asm volatile("ldmatrix.sync.aligned.m8n8.x4.trans.shared.b16 {%0,%1,%2,%3}, [%4];"
                 : "=r"(d[0]), "=r"(d[1]), "=r"(d[2]), "=r"(d[3]) : "r"(a));
}
__device__ __forceinline__ void mma_f16(float* c, const uint32_t* a,
                                        const uint32_t* b) {
    asm volatile(
        "mma.sync.aligned.m16n8k16.row.col.f32.f16.f16.f32 "
        "{%0,%1,%2,%3}, {%4,%5,%6,%7}, {%8,%9}, {%0,%1,%2,%3};"
        : "+f"(c[0]), "+f"(c[1]), "+f"(c[2]), "+f"(c[3])
        : "r"(a[0]), "r"(a[1]), "r"(a[2]), "r"(a[3]), "r"(b[0]), "r"(b[1]));
}
__device__ __forceinline__ void cp16(uint32_t saddr, const void* gaddr) {
    asm volatile("cp.async.cg.shared.global [%0], [%1], 16;"
                 :: "r"(saddr), "l"(gaddr) : "memory");
}
#define CP_COMMIT() asm volatile("cp.async.commit_group;" ::: "memory")
#define CP_WAIT0()  asm volatile("cp.async.wait_group 0;" ::: "memory")

// ---------------- staging kernels ------------------------------------------
__global__ void conv_a3_kernel(const float* __restrict__ Q,
                               const float* __restrict__ K,
                               const float* __restrict__ V) {
    const float* src = (blockIdx.y == 0) ? Q : (blockIdx.y == 1) ? K : V;
    __half* out = g_ah3 + (size_t)blockIdx.y * N_ * E_;
    size_t i = ((size_t)blockIdx.x * 256 + threadIdx.x) * 4;
    float4 v = *(const float4*)(src + i);
    *(__half2*)(out + i)     = __floats2half2_rn(v.x, v.y);
    *(__half2*)(out + i + 2) = __floats2half2_rn(v.z, v.w);
}

__global__ void conv_wt4_kernel(const float* __restrict__ W0,
                                const float* __restrict__ W1,
                                const float* __restrict__ W2,
                                const float* __restrict__ W3) {
    __shared__ __half t[32][33];
    const float* W = (blockIdx.z == 0) ? W0 : (blockIdx.z == 1) ? W1
                   : (blockIdx.z == 2) ? W2 : W3;
    __half* WT = g_wth4 + (size_t)blockIdx.z * E_ * HD_;
    int n0 = blockIdx.x * 32, k0 = blockIdx.y * 32;
    int tx = threadIdx.x, ty = threadIdx.y;
#pragma unroll
    for (int i = 0; i < 4; i++)
        t[ty + i * 8][tx] = __float2half(W[(size_t)(k0 + ty + i * 8) * HD_ + n0 + tx]);
    __syncthreads();
#pragma unroll
    for (int i = 0; i < 4; i++)
        WT[(size_t)(n0 + ty + i * 8) * E_ + k0 + tx] = t[tx][ty + i * 8];
}

// ============ fp16 ldmatrix GEMM (R6/R8-validated) =========================
__global__ void __launch_bounds__(256) gemm_h_kernel(
    const __half* __restrict__ Ah, const __half* __restrict__ WT,
    const float* __restrict__ bias, float* __restrict__ outp, int sel) {

    __shared__ __half sA[2][128 * 32];
    __shared__ __half sB[2][128 * 32];

    const int tid = threadIdx.x;
    const int wid = tid >> 5, lane = tid & 31;
    const int m0 = blockIdx.y * 128, c0 = blockIdx.x * 128;
    const int warpM = wid & 1, warpN = wid >> 1;
    const int g = lane >> 2, tq = lane & 3;

    const uint32_t sAb0 = cvta_smem(sA[0]), sBb0 = cvta_smem(sB[0]);

    const int l_row = tid >> 2;
    const int l_c   = tid & 3;

    uint4 aregs[2], bregs[2];
    auto ldg_chunk = [&](int k0) {
#pragma unroll
        for (int e = 0; e < 2; e++) {
            int row = l_row + e * 64;
            aregs[e] = *(const uint4*)(Ah + (size_t)(m0 + row) * E_ + k0 + l_c * 8);
            bregs[e] = *(const uint4*)(WT + (size_t)(c0 + row) * E_ + k0 + l_c * 8);
        }
    };
    auto sts_chunk = [&](int buf) {
#pragma unroll
        for (int e = 0; e < 2; e++) {
            int row = l_row + e * 64;
            int cs = (l_c ^ (row & 3)) * 8;
            *(uint4*)(sA[buf] + row * 32 + cs) = aregs[e];
            *(uint4*)(sB[buf] + row * 32 + cs) = bregs[e];
        }
    };

    const int lr8 = (lane & 7) + ((lane >> 3) & 1) * 8;
    const int ls4 = lane >> 4;
    int a_rr[4], b_rr[2];
#pragma unroll
    for (int i = 0; i < 4; i++) a_rr[i] = warpM * 64 + i * 16 + lr8;
#pragma unroll
    for (int j = 0; j < 2; j++) b_rr[j] = warpN * 32 + j * 16 + lr8;

    float c[4][4][4] = {};

    ldg_chunk(0);
    sts_chunk(0);
    __syncthreads();

    for (int ch = 0; ch < 32; ch++) {
        const int buf = ch & 1;
        if (ch < 31) ldg_chunk((ch + 1) * 32);

        const uint32_t ab = sAb0 + buf * (128 * 32 * 2);
        const uint32_t bb = sBb0 + buf * (128 * 32 * 2);
#pragma unroll
        for (int kt = 0; kt < 2; kt++) {
            uint32_t af[4][4];
            uint32_t bf[4][2];
#pragma unroll
            for (int i = 0; i < 4; i++) {
                int cc = ((kt << 1) | ls4) ^ (a_rr[i] & 3);
                ldmx4(af[i], ab + a_rr[i] * 64 + cc * 16);
            }
#pragma unroll
            for (int jj = 0; jj < 2; jj++) {
                int cc = ((kt << 1) | ls4) ^ (b_rr[jj] & 3);
                uint32_t t4[4];
                ldmx4(t4, bb + b_rr[jj] * 64 + cc * 16);
                bf[jj * 2][0] = t4[0]; bf[jj * 2 + 1][0] = t4[1];
                bf[jj * 2][1] = t4[2]; bf[jj * 2 + 1][1] = t4[3];
            }
#pragma unroll
            for (int i = 0; i < 4; i++)
#pragma unroll
                for (int j = 0; j < 4; j++)
                    mma_f16(c[i][j], af[i], bf[j]);
        }

        if (ch < 31) sts_chunk(buf ^ 1);
        __syncthreads();
    }

    const float osc = (sel == 0) ? SCALE_ : 1.0f;
    __half* hdst = (sel == 0) ? g_qh : (sel == 1) ? g_kh : g_vh;
#pragma unroll
    for (int i = 0; i < 4; i++) {
        int rtop = m0 + warpM * 64 + i * 16 + g;
        int rbot = rtop + 8;
#pragma unroll
        for (int j = 0; j < 4; j++) {
            int coln = c0 + warpN * 32 + j * 8 + tq * 2;
            float2 bb2 = *(const float2*)(bias + coln);
            float v00 = c[i][j][0] + bb2.x, v01 = c[i][j][1] + bb2.y;
            float v10 = c[i][j][2] + bb2.x, v11 = c[i][j][3] + bb2.y;
            if (sel < 3) {
                int hI = coln >> 6, dI = coln & 63;
                int b0I = rtop >> 11, s0I = rtop & (S_ - 1);
                int b1I = rbot >> 11, s1I = rbot & (S_ - 1);
                *(__half2*)(hdst + (((size_t)b0I * H_ + hI) * S_ + s0I) * D_ + dI) =
                    __floats2half2_rn(v00 * osc, v01 * osc);
                *(__half2*)(hdst + (((size_t)b1I * H_ + hI) * S_ + s1I) * D_ + dI) =
                    __floats2half2_rn(v10 * osc, v11 * osc);
            } else {
                *(float2*)(outp + (size_t)rtop * HD_ + coln) = make_float2(v00, v01);
                *(float2*)(outp + (size_t)rbot * HD_ + coln) = make_float2(v10, v11);
            }
        }
    }
}

// ---------------- attention -------------------------------------------------
// Pass 1 (1 barrier/iter): cp.async K tile, mma scores, mask+exp DIRECTLY on
// fragments, e (fp16, x1/16) -> g_eh, row sums via quad-shuffle + smem atomics.
// Pass 2: cp.async V tile; e-read, p=e*(16/l) -> prob fp32 + hP frags -> ctx mma.
#define ATTN_SMEM (8192 + 16384 + 8192 + 256)

__global__ void __launch_bounds__(256, 3) attn_kernel(
    const void* __restrict__ mask, float* __restrict__ prob) {

    extern __shared__ char smraw[];
    __half* hQ = (__half*)smraw;                  // 8 KB
    __half* hK = hQ + 4096;                       // 2 x 8 KB (K pass1 / V pass2)
    __half* hP = hK + 8192;                       // 8 KB (pass2 P tile)
    float*  sRow = (float*)(smraw + 32768);       // 64 row-sum accumulators

    const int tid = threadIdx.x, tx = tid & 15, ty = tid >> 4;
    const int wid = tid >> 5, lane = tid & 31;
    const int warpM = wid & 1, warpN = wid >> 1;
    const int g = lane >> 2, tq = lane & 3;
    const int bh = blockIdx.y, q0 = blockIdx.x * 64;
    const int bI = bh >> 4, hI = bh & 15;

    __shared__ int s_mm;
    {
        unsigned int v = ((const unsigned int*)mask)[tid];
        int isf = __syncthreads_or(v == 0x3F800000u);
        int big = __syncthreads_or(v > 1u);
        if (tid == 0) s_mm = isf ? 2 : (big ? 0 : 1);
    }
    if (tid < 64) sRow[tid] = 0.f;

    const __half* qg = g_qh + (size_t)bh * S_ * D_ + (size_t)q0 * D_;
    const __half* kg = g_kh + (size_t)bh * S_ * D_;
    const __half* vg = g_vh + (size_t)bh * S_ * D_;
    float* sc = prob + ((size_t)bh * S_ + q0) * S_;
    __half* eg = g_eh + ((size_t)bh * S_ + q0) * S_;

    const uint32_t hQb = cvta_smem(hQ), hKb = cvta_smem(hK);
    const uint32_t hPb = cvta_smem(hP);

    const int tl_row = tid >> 2;
    {
#pragma unroll
        for (int e = 0; e < 2; e++) {
            int c = (tid & 3) * 2 + e;
            uint4 v = *(const uint4*)(qg + (size_t)tl_row * 64 + c * 8);
            *(uint4*)(hQ + tl_row * 64 + ((c ^ (tl_row & 7)) * 8)) = v;
        }
    }
    auto load_async = [&](int buf, const __half* src, int k0) {
#pragma unroll
        for (int e = 0; e < 2; e++) {
            int c = (tid & 3) * 2 + e;
            cp16(hKb + buf * 8192 + tl_row * 128 + ((c ^ (tl_row & 7)) * 16),
                 src + (size_t)(k0 + tl_row) * 64 + c * 8);
        }
        CP_COMMIT();
    };

    const int lr8 = (lane & 7) + ((lane >> 3) & 1) * 8;
    const int ls4 = lane >> 4;
    int q_rr[2];
#pragma unroll
    for (int i = 0; i < 2; i++) q_rr[i] = warpM * 32 + i * 16 + lr8;
    const int k_rr = warpN * 16 + lr8;
    const int v_cc_raw = warpN * 2 + ls4;

    const int mm = s_mm;

    // =================== pass 1: exp-scores + row sums ====================
    load_async(0, kg, 0);
    for (int kt0 = 0; kt0 < 32; kt0++) {
        const int buf = kt0 & 1;
        CP_WAIT0();
        __syncthreads();
        if (kt0 < 31) load_async(buf ^ 1, kg, (kt0 + 1) * 64);

        float cs[2][2][4] = {};
        const uint32_t kb = hKb + buf * 8192;
#pragma unroll
        for (int kt = 0; kt < 4; kt++) {
            uint32_t af[2][4], bf[2][2], t4[4];
#pragma unroll
            for (int i = 0; i < 2; i++) {
                int cc = ((kt << 1) | ls4) ^ (q_rr[i] & 7);
                ldmx4(af[i], hQb + q_rr[i] * 128 + cc * 16);
            }
            {
                int cc = ((kt << 1) | ls4) ^ (k_rr & 7);
                ldmx4(t4, kb + k_rr * 128 + cc * 16);
                bf[0][0] = t4[0]; bf[1][0] = t4[1];
                bf[0][1] = t4[2]; bf[1][1] = t4[3];
            }
#pragma unroll
            for (int i = 0; i < 2; i++)
#pragma unroll
                for (int j = 0; j < 2; j++)
                    mma_f16(cs[i][j], af[i], bf[j]);
        }

        // mask + exp + e-store directly on fragments; row sums via shuffles
        const int k0 = kt0 * 64;
#pragma unroll
        for (int i = 0; i < 2; i++) {
            const int r0 = warpM * 32 + i * 16 + g;    // local rows r0, r0+8
            const size_t gr0 = (size_t)bI * S_ + q0 + r0;
            float rs0 = 0.f, rs1 = 0.f;
#pragma unroll
            for (int j = 0; j < 2; j++) {
                const int c0 = warpN * 16 + j * 8 + tq * 2;
                float a0 = cs[i][j][0], a1 = cs[i][j][1];
                float a2 = cs[i][j][2], a3 = cs[i][j][3];
                const size_t m0off = gr0 * S_ + k0 + c0;
                const size_t m1off = m0off + 8 * S_;
                if (mm == 0) {
                    const unsigned char* mp = (const unsigned char*)mask;
                    uchar2 u0 = *(const uchar2*)(mp + m0off);
                    uchar2 u1 = *(const uchar2*)(mp + m1off);
                    if (u0.x) a0 = NEG_;
                    if (u0.y) a1 = NEG_;
                    if (u1.x) a2 = NEG_;
                    if (u1.y) a3 = NEG_;
                } else if (mm == 1) {
                    const int* mp = (const int*)mask;
                    int2 u0 = *(const int2*)(mp + m0off);
                    int2 u1 = *(const int2*)(mp + m1off);
                    if (u0.x) a0 = NEG_;
                    if (u0.y) a1 = NEG_;
                    if (u1.x) a2 = NEG_;
                    if (u1.y) a3 = NEG_;
                } else {
                    const float* mp = (const float*)mask;
                    float2 u0 = *(const float2*)(mp + m0off);
                    float2 u1 = *(const float2*)(mp + m1off);
                    if (u0.x != 0.f) a0 = NEG_;
                    if (u0.y != 0.f) a1 = NEG_;
                    if (u1.x != 0.f) a2 = NEG_;
                    if (u1.y != 0.f) a3 = NEG_;
                }
                float e0 = __expf(a0), e1 = __expf(a1);
                float e2 = __expf(a2), e3 = __expf(a3);
                rs0 += e0 + e1;
                rs1 += e2 + e3;
                *(__half2*)(eg + (size_t)r0 * S_ + k0 + c0) =
                    __floats2half2_rn(e0 * 0.0625f, e1 * 0.0625f);
                *(__half2*)(eg + (size_t)(r0 + 8) * S_ + k0 + c0) =
                    __floats2half2_rn(e2 * 0.0625f, e3 * 0.0625f);
            }
            rs0 += __shfl_xor_sync(0xffffffffu, rs0, 1);
            rs0 += __shfl_xor_sync(0xffffffffu, rs0, 2);
            rs1 += __shfl_xor_sync(0xffffffffu, rs1, 1);
            rs1 += __shfl_xor_sync(0xffffffffu, rs1, 2);
            if (tq == 0) {
                atomicAdd(sRow + r0, rs0);
                atomicAdd(sRow + r0 + 8, rs1);
            }
        }
    }
    __syncthreads();

    // =================== pass 2: prob + ctx = P @ V =======================
    float il16[4];
#pragma unroll
    for (int ir = 0; ir < 4; ir++) il16[ir] = 16.0f / sRow[ty * 4 + ir];
    float ctx[2][2][4] = {};

    load_async(0, vg, 0);
    for (int kt0 = 0; kt0 < 32; kt0++) {
        const int buf = kt0 & 1;
        CP_WAIT0();
        __syncthreads();
        if (kt0 < 31) load_async(buf ^ 1, vg, (kt0 + 1) * 64);

        const int k0 = kt0 * 64;
#pragma unroll
        for (int ir = 0; ir < 4; ir++) {
            int row = ty * 4 + ir;
            uint2 ev = *(const uint2*)(eg + (size_t)row * S_ + k0 + tx * 4);
            float2 f0 = __half22float2(*(__half2*)&ev.x);
            float2 f1 = __half22float2(*(__half2*)&ev.y);
            float4 p4;
            p4.x = f0.x * il16[ir];
            p4.y = f0.y * il16[ir];
            p4.z = f1.x * il16[ir];
            p4.w = f1.y * il16[ir];
            *(float4*)(sc + (size_t)row * S_ + k0 + tx * 4) = p4;  // prob out
            int c = tx >> 1;
            __half* pp = hP + row * 64 + ((c ^ (row & 7)) * 8) + (tx & 1) * 4;
            *(__half2*)(pp)     = __floats2half2_rn(p4.x, p4.y);
            *(__half2*)(pp + 2) = __floats2half2_rn(p4.z, p4.w);
        }
        __syncthreads();

        const uint32_t vb = hKb + buf * 8192;
#pragma unroll
        for (int kt = 0; kt < 4; kt++) {
            uint32_t pf[2][4], vf[2][2], t4[4];
#pragma unroll
            for (int i = 0; i < 2; i++) {
                int cc = ((kt << 1) | ls4) ^ (q_rr[i] & 7);
                ldmx4(pf[i], hPb + q_rr[i] * 128 + cc * 16);
            }
            {
                int rr = kt * 16 + lr8;
                int cc = v_cc_raw ^ (rr & 7);
                ldmx4t(t4, vb + rr * 128 + cc * 16);
                vf[0][0] = t4[0]; vf[0][1] = t4[1];
                vf[1][0] = t4[2]; vf[1][1] = t4[3];
            }
#pragma unroll
            for (int i = 0; i < 2; i++)
#pragma unroll
                for (int j = 0; j < 2; j++)
                    mma_f16(ctx[i][j], pf[i], vf[j]);
        }
    }

    // ---- store ctx (fp16) -------------------------------------------------
#pragma unroll
    for (int i = 0; i < 2; i++) {
        int r0 = q0 + warpM * 32 + i * 16 + g;
#pragma unroll
        for (int j = 0; j < 2; j++) {
            int cl = hI * 64 + warpN * 16 + j * 8 + tq * 2;
            *(__half2*)(g_ctxh + ((size_t)bI * S_ + r0) * HD_ + cl) =
                __floats2half2_rn(ctx[i][j][0], ctx[i][j][1]);
            *(__half2*)(g_ctxh + ((size_t)bI * S_ + r0 + 8) * HD_ + cl) =
                __floats2half2_rn(ctx[i][j][2], ctx[i][j][3]);
        }
    }
}

// ---------------- launcher ------------------------------------------------
extern "C" void kernel_launch(void* const* d_in, const int* in_sizes, int n_in,
                              void* d_out, int out_size) {
    const float* Q  = (const float*)d_in[0];
    const float* K  = (const float*)d_in[1];
    const float* V  = (const float*)d_in[2];
    const void*  mask = d_in[3];
    const float* WQ = (const float*)d_in[4];
    const float* bQ = (const float*)d_in[5];
    const float* WK = (const float*)d_in[6];
    const float* bK = (const float*)d_in[7];
    const float* WV = (const float*)d_in[8];
    const float* bV = (const float*)d_in[9];
    const float* WO = (const float*)d_in[10];
    const float* bO = (const float*)d_in[11];

    float* y    = (float*)d_out;
    float* prob = y + (size_t)N_ * E_;

    __half *ah, *wth, *ctxh;
    cudaGetSymbolAddress((void**)&ah,   g_ah3);
    cudaGetSymbolAddress((void**)&wth,  g_wth4);
    cudaGetSymbolAddress((void**)&ctxh, g_ctxh);

    cudaFuncSetAttribute(attn_kernel,
                         cudaFuncAttributeMaxDynamicSharedMemorySize, ATTN_SMEM);

    dim3 blk(256);
    dim3 gproj(HD_ / 128, N_ / 128);

    conv_a3_kernel<<<dim3(4096, 3), 256>>>(Q, K, V);
    conv_wt4_kernel<<<dim3(32, 32, 4), dim3(32, 8)>>>(WQ, WK, WV, WO);

    gemm_h_kernel<<<gproj, blk>>>(ah,                       wth,                        bQ, nullptr, 0);
    gemm_h_kernel<<<gproj, blk>>>(ah + (size_t)N_ * E_,     wth + (size_t)E_ * HD_,     bK, nullptr, 1);
    gemm_h_kernel<<<gproj, blk>>>(ah + (size_t)2 * N_ * E_, wth + (size_t)2 * E_ * HD_, bV, nullptr, 2);

    attn_kernel<<<dim3(S_ / 64, B_ * H_), blk, ATTN_SMEM>>>(mask, prob);

    gemm_h_kernel<<<gproj, blk>>>(ctxh, wth + (size_t)3 * E_ * HD_, bO, y, 3);
}

// round 11
// speedup vs baseline: 1.2003x; 1.2003x over previous
#include <cuda_runtime.h>
#include <cuda_fp16.h>
#include <cstdint>

// Problem constants
#define B_   2
#define S_   2048
#define E_   1024
#define H_   16
#define D_   64
#define HD_  1024
#define N_   4096            // B*S
#define SCALE_ 0.125f        // 1/sqrt(64), exact power of two
#define NEG_  -1e9f

// ---------------- scratch (device globals; no allocations allowed) -------
__device__ __half g_qh[(size_t)B_ * H_ * S_ * D_];   // [bh][s][d], pre-scaled
__device__ __half g_kh[(size_t)B_ * H_ * S_ * D_];
__device__ __half g_vh[(size_t)B_ * H_ * S_ * D_];
__device__ __half g_ctxh[(size_t)N_ * HD_];          // [b*S+s][h*D+d]
__device__ __half g_ah3[(size_t)3 * N_ * E_];        // staged Q/K/V inputs (fp16)
__device__ __half g_wth4[(size_t)4 * E_ * HD_];      // staged W^T x4 (fp16)
__device__ __half g_eh[(size_t)B_ * H_ * S_ * S_];   // exp-scores / 16 (fp16)

// ---------------- helpers --------------------------------------------------
__device__ __forceinline__ uint32_t cvta_smem(const void* p) {
    uint32_t a;
    asm("{ .reg .u64 t; cvta.to.shared.u64 t, %1; cvt.u32.u64 %0, t; }"
        : "=r"(a) : "l"(p));
    return a;
}
__device__ __forceinline__ void ldmx4(uint32_t* d, uint32_t a) {
    asm volatile("ldmatrix.sync.aligned.m8n8.x4.shared.b16 {%0,%1,%2,%3}, [%4];"
                 : "=r"(d[0]), "=r"(d[1]), "=r"(d[2]), "=r"(d[3]) : "r"(a));
}
__device__ __forceinline__ void ldmx4t(uint32_t* d, uint32_t a) {
    asm volatile("ldmatrix.sync.aligned.m8n8.x4.trans.shared.b16 {%0,%1,%2,%3}, [%4];"
                 : "=r"(d[0]), "=r"(d[1]), "=r"(d[2]), "=r"(d[3]) : "r"(a));
}
__device__ __forceinline__ void mma_f16(float* c, const uint32_t* a,
                                        const uint32_t* b) {
    asm volatile(
        "mma.sync.aligned.m16n8k16.row.col.f32.f16.f16.f32 "
        "{%0,%1,%2,%3}, {%4,%5,%6,%7}, {%8,%9}, {%0,%1,%2,%3};"
        : "+f"(c[0]), "+f"(c[1]), "+f"(c[2]), "+f"(c[3])
        : "r"(a[0]), "r"(a[1]), "r"(a[2]), "r"(a[3]), "r"(b[0]), "r"(b[1]));
}
__device__ __forceinline__ void cp16(uint32_t saddr, const void* gaddr) {
    asm volatile("cp.async.cg.shared.global [%0], [%1], 16;"
                 :: "r"(saddr), "l"(gaddr) : "memory");
}
#define CP_COMMIT() asm volatile("cp.async.commit_group;" ::: "memory")
#define CP_WAIT0()  asm volatile("cp.async.wait_group 0;" ::: "memory")

// ---------------- staging kernels ------------------------------------------
__global__ void conv_a3_kernel(const float* __restrict__ Q,
                               const float* __restrict__ K,
                               const float* __restrict__ V) {
    const float* src = (blockIdx.y == 0) ? Q : (blockIdx.y == 1) ? K : V;
    __half* out = g_ah3 + (size_t)blockIdx.y * N_ * E_;
    size_t i = ((size_t)blockIdx.x * 256 + threadIdx.x) * 4;
    float4 v = *(const float4*)(src + i);
    *(__half2*)(out + i)     = __floats2half2_rn(v.x, v.y);
    *(__half2*)(out + i + 2) = __floats2half2_rn(v.z, v.w);
}

__global__ void conv_wt4_kernel(const float* __restrict__ W0,
                                const float* __restrict__ W1,
                                const float* __restrict__ W2,
                                const float* __restrict__ W3) {
    __shared__ __half t[32][33];
    const float* W = (blockIdx.z == 0) ? W0 : (blockIdx.z == 1) ? W1
                   : (blockIdx.z == 2) ? W2 : W3;
    __half* WT = g_wth4 + (size_t)blockIdx.z * E_ * HD_;
    int n0 = blockIdx.x * 32, k0 = blockIdx.y * 32;
    int tx = threadIdx.x, ty = threadIdx.y;
#pragma unroll
    for (int i = 0; i < 4; i++)
        t[ty + i * 8][tx] = __float2half(W[(size_t)(k0 + ty + i * 8) * HD_ + n0 + tx]);
    __syncthreads();
#pragma unroll
    for (int i = 0; i < 4; i++)
        WT[(size_t)(n0 + ty + i * 8) * E_ + k0 + tx] = t[tx][ty + i * 8];
}

// ============ fp16 ldmatrix GEMM — 80B-padded rows (conflict-free ldmatrix) =
// Tiles: 128 rows x 32 k halves stored with row stride 40 halves (80 B).
// Bank group per ldmatrix row = (20*row + 4*cc) mod 32 -> 8 distinct for any
// 8-row phase; no XOR swizzle needed.
#define RSTRIDE 40
#define TILEBUF (128 * RSTRIDE)

__global__ void __launch_bounds__(256) gemm_h_kernel(
    const __half* __restrict__ Ah, const __half* __restrict__ WT,
    const float* __restrict__ bias, float* __restrict__ outp, int sel) {

    __shared__ __half sA[2][TILEBUF];
    __shared__ __half sB[2][TILEBUF];

    const int tid = threadIdx.x;
    const int wid = tid >> 5, lane = tid & 31;
    const int m0 = blockIdx.y * 128, c0 = blockIdx.x * 128;
    const int warpM = wid & 1, warpN = wid >> 1;
    const int g = lane >> 2, tq = lane & 3;

    const uint32_t sAb0 = cvta_smem(sA[0]), sBb0 = cvta_smem(sB[0]);

    const int l_row = tid >> 2;
    const int l_c   = tid & 3;

    uint4 aregs[2], bregs[2];
    auto ldg_chunk = [&](int k0) {
#pragma unroll
        for (int e = 0; e < 2; e++) {
            int row = l_row + e * 64;
            aregs[e] = *(const uint4*)(Ah + (size_t)(m0 + row) * E_ + k0 + l_c * 8);
            bregs[e] = *(const uint4*)(WT + (size_t)(c0 + row) * E_ + k0 + l_c * 8);
        }
    };
    auto sts_chunk = [&](int buf) {
#pragma unroll
        for (int e = 0; e < 2; e++) {
            int row = l_row + e * 64;
            *(uint4*)(sA[buf] + row * RSTRIDE + l_c * 8) = aregs[e];
            *(uint4*)(sB[buf] + row * RSTRIDE + l_c * 8) = bregs[e];
        }
    };

    const int lr8 = (lane & 7) + ((lane >> 3) & 1) * 8;
    const int ls4 = lane >> 4;
    int a_rr[4], b_rr[2];
#pragma unroll
    for (int i = 0; i < 4; i++) a_rr[i] = warpM * 64 + i * 16 + lr8;
#pragma unroll
    for (int j = 0; j < 2; j++) b_rr[j] = warpN * 32 + j * 16 + lr8;

    float c[4][4][4] = {};

    ldg_chunk(0);
    sts_chunk(0);
    __syncthreads();

    for (int ch = 0; ch < 32; ch++) {
        const int buf = ch & 1;
        if (ch < 31) ldg_chunk((ch + 1) * 32);

        const uint32_t ab = sAb0 + buf * (TILEBUF * 2);
        const uint32_t bb = sBb0 + buf * (TILEBUF * 2);
#pragma unroll
        for (int kt = 0; kt < 2; kt++) {
            const int cc = (kt << 1) | ls4;
            uint32_t af[4][4];
            uint32_t bf[4][2];
#pragma unroll
            for (int i = 0; i < 4; i++)
                ldmx4(af[i], ab + a_rr[i] * (RSTRIDE * 2) + cc * 16);
#pragma unroll
            for (int jj = 0; jj < 2; jj++) {
                uint32_t t4[4];
                ldmx4(t4, bb + b_rr[jj] * (RSTRIDE * 2) + cc * 16);
                bf[jj * 2][0] = t4[0]; bf[jj * 2 + 1][0] = t4[1];
                bf[jj * 2][1] = t4[2]; bf[jj * 2 + 1][1] = t4[3];
            }
#pragma unroll
            for (int i = 0; i < 4; i++)
#pragma unroll
                for (int j = 0; j < 4; j++)
                    mma_f16(c[i][j], af[i], bf[j]);
        }

        if (ch < 31) sts_chunk(buf ^ 1);
        __syncthreads();
    }

    const float osc = (sel == 0) ? SCALE_ : 1.0f;
    __half* hdst = (sel == 0) ? g_qh : (sel == 1) ? g_kh : g_vh;
#pragma unroll
    for (int i = 0; i < 4; i++) {
        int rtop = m0 + warpM * 64 + i * 16 + g;
        int rbot = rtop + 8;
#pragma unroll
        for (int j = 0; j < 4; j++) {
            int coln = c0 + warpN * 32 + j * 8 + tq * 2;
            float2 bb2 = *(const float2*)(bias + coln);
            float v00 = c[i][j][0] + bb2.x, v01 = c[i][j][1] + bb2.y;
            float v10 = c[i][j][2] + bb2.x, v11 = c[i][j][3] + bb2.y;
            if (sel < 3) {
                int hI = coln >> 6, dI = coln & 63;
                int b0I = rtop >> 11, s0I = rtop & (S_ - 1);
                int b1I = rbot >> 11, s1I = rbot & (S_ - 1);
                *(__half2*)(hdst + (((size_t)b0I * H_ + hI) * S_ + s0I) * D_ + dI) =
                    __floats2half2_rn(v00 * osc, v01 * osc);
                *(__half2*)(hdst + (((size_t)b1I * H_ + hI) * S_ + s1I) * D_ + dI) =
                    __floats2half2_rn(v10 * osc, v11 * osc);
            } else {
                *(float2*)(outp + (size_t)rtop * HD_ + coln) = make_float2(v00, v01);
                *(float2*)(outp + (size_t)rbot * HD_ + coln) = make_float2(v10, v11);
            }
        }
    }
}

// ---------------- attention: R9 version verbatim (747 µs best) -------------
#define ATTN_SMEM (8192 + 2 * 8192 + 64 * 68 * 4)

__global__ void __launch_bounds__(256) attn_kernel(
    const void* __restrict__ mask, float* __restrict__ prob) {

    extern __shared__ char smraw[];
    __half* hQ = (__half*)smraw;                  // 8 KB
    __half* hK = hQ + 4096;                       // 2 x 8 KB (K pass1 / V pass2)
    float*  sS = (float*)(smraw + 24576);         // 64x68 fp32 (pass1)
    __half* hP = (__half*)sS;                     // pass2 alias

    const int tid = threadIdx.x, tx = tid & 15, ty = tid >> 4;
    const int wid = tid >> 5, lane = tid & 31;
    const int warpM = wid & 1, warpN = wid >> 1;
    const int g = lane >> 2, tq = lane & 3;
    const int bh = blockIdx.y, q0 = blockIdx.x * 64;
    const int bI = bh >> 4, hI = bh & 15;

    __shared__ int s_mm;
    {
        unsigned int v = ((const unsigned int*)mask)[tid];
        int isf = __syncthreads_or(v == 0x3F800000u);
        int big = __syncthreads_or(v > 1u);
        if (tid == 0) s_mm = isf ? 2 : (big ? 0 : 1);
    }

    const __half* qg = g_qh + (size_t)bh * S_ * D_ + (size_t)q0 * D_;
    const __half* kg = g_kh + (size_t)bh * S_ * D_;
    const __half* vg = g_vh + (size_t)bh * S_ * D_;
    float* sc = prob + ((size_t)bh * S_ + q0) * S_;
    __half* eg = g_eh + ((size_t)bh * S_ + q0) * S_;

    const uint32_t hQb = cvta_smem(hQ), hKb = cvta_smem(hK);
    const uint32_t hPb = cvta_smem(hP);

    const int tl_row = tid >> 2;
    {
#pragma unroll
        for (int e = 0; e < 2; e++) {
            int c = (tid & 3) * 2 + e;
            uint4 v = *(const uint4*)(qg + (size_t)tl_row * 64 + c * 8);
            *(uint4*)(hQ + tl_row * 64 + ((c ^ (tl_row & 7)) * 8)) = v;
        }
    }
    auto load_async = [&](int buf, const __half* src, int k0) {
#pragma unroll
        for (int e = 0; e < 2; e++) {
            int c = (tid & 3) * 2 + e;
            cp16(hKb + buf * 8192 + tl_row * 128 + ((c ^ (tl_row & 7)) * 16),
                 src + (size_t)(k0 + tl_row) * 64 + c * 8);
        }
        CP_COMMIT();
    };

    const int lr8 = (lane & 7) + ((lane >> 3) & 1) * 8;
    const int ls4 = lane >> 4;
    int q_rr[2];
#pragma unroll
    for (int i = 0; i < 2; i++) q_rr[i] = warpM * 32 + i * 16 + lr8;
    const int k_rr = warpN * 16 + lr8;
    const int v_cc_raw = warpN * 2 + ls4;

    const int mm = s_mm;
    float l[4] = {0.f, 0.f, 0.f, 0.f};

    // =================== pass 1: exp-scores + row sums ====================
    load_async(0, kg, 0);
    for (int kt0 = 0; kt0 < 32; kt0++) {
        const int buf = kt0 & 1;
        CP_WAIT0();
        __syncthreads();
        if (kt0 < 31) load_async(buf ^ 1, kg, (kt0 + 1) * 64);

        float cs[2][2][4] = {};
        const uint32_t kb = hKb + buf * 8192;
#pragma unroll
        for (int kt = 0; kt < 4; kt++) {
            uint32_t af[2][4], bf[2][2], t4[4];
#pragma unroll
            for (int i = 0; i < 2; i++) {
                int cc = ((kt << 1) | ls4) ^ (q_rr[i] & 7);
                ldmx4(af[i], hQb + q_rr[i] * 128 + cc * 16);
            }
            {
                int cc = ((kt << 1) | ls4) ^ (k_rr & 7);
                ldmx4(t4, kb + k_rr * 128 + cc * 16);
                bf[0][0] = t4[0]; bf[1][0] = t4[1];
                bf[0][1] = t4[2]; bf[1][1] = t4[3];
            }
#pragma unroll
            for (int i = 0; i < 2; i++)
#pragma unroll
                for (int j = 0; j < 2; j++)
                    mma_f16(cs[i][j], af[i], bf[j]);
        }
#pragma unroll
        for (int i = 0; i < 2; i++) {
            int r0 = warpM * 32 + i * 16 + g;
#pragma unroll
            for (int j = 0; j < 2; j++) {
                int cl = warpN * 16 + j * 8 + tq * 2;
                *(float2*)(sS + r0 * 68 + cl)       = make_float2(cs[i][j][0], cs[i][j][1]);
                *(float2*)(sS + (r0 + 8) * 68 + cl) = make_float2(cs[i][j][2], cs[i][j][3]);
            }
        }
        __syncthreads();

        const int k0 = kt0 * 64;
#pragma unroll
        for (int ir = 0; ir < 4; ir++) {
            int row = ty * 4 + ir;
            float4 s4 = *(const float4*)(sS + row * 68 + tx * 4);
            float acc[4] = {s4.x, s4.y, s4.z, s4.w};
            size_t moff = ((size_t)bI * S_ + q0 + row) * S_ + k0 + tx * 4;
            if (mm == 0) {
                uchar4 u = *(const uchar4*)((const unsigned char*)mask + moff);
                if (u.x) acc[0] = NEG_;
                if (u.y) acc[1] = NEG_;
                if (u.z) acc[2] = NEG_;
                if (u.w) acc[3] = NEG_;
            } else if (mm == 1) {
                int4 u = *(const int4*)((const int*)mask + moff);
                if (u.x) acc[0] = NEG_;
                if (u.y) acc[1] = NEG_;
                if (u.z) acc[2] = NEG_;
                if (u.w) acc[3] = NEG_;
            } else {
                float4 u = *(const float4*)((const float*)mask + moff);
                if (u.x != 0.f) acc[0] = NEG_;
                if (u.y != 0.f) acc[1] = NEG_;
                if (u.z != 0.f) acc[2] = NEG_;
                if (u.w != 0.f) acc[3] = NEG_;
            }
            float4 e4;
            e4.x = __expf(acc[0]);
            e4.y = __expf(acc[1]);
            e4.z = __expf(acc[2]);
            e4.w = __expf(acc[3]);
            __half2 h0 = __floats2half2_rn(e4.x * 0.0625f, e4.y * 0.0625f);
            __half2 h1 = __floats2half2_rn(e4.z * 0.0625f, e4.w * 0.0625f);
            uint2 ev;
            ev.x = *(uint32_t*)&h0;
            ev.y = *(uint32_t*)&h1;
            *(uint2*)(eg + (size_t)row * S_ + k0 + tx * 4) = ev;
            float ps = e4.x + e4.y + e4.z + e4.w;
#pragma unroll
            for (int o = 8; o; o >>= 1)
                ps += __shfl_xor_sync(0xffffffffu, ps, o);
            l[ir] += ps;
        }
    }

    // =================== pass 2: prob + ctx = P @ V =======================
    float il16[4];
#pragma unroll
    for (int ir = 0; ir < 4; ir++) il16[ir] = 16.0f / l[ir];
    float ctx[2][2][4] = {};

    load_async(0, vg, 0);
    for (int kt0 = 0; kt0 < 32; kt0++) {
        const int buf = kt0 & 1;
        CP_WAIT0();
        __syncthreads();
        if (kt0 < 31) load_async(buf ^ 1, vg, (kt0 + 1) * 64);

        const int k0 = kt0 * 64;
#pragma unroll
        for (int ir = 0; ir < 4; ir++) {
            int row = ty * 4 + ir;
            uint2 ev = *(const uint2*)(eg + (size_t)row * S_ + k0 + tx * 4);
            float2 f0 = __half22float2(*(__half2*)&ev.x);
            float2 f1 = __half22float2(*(__half2*)&ev.y);
            float4 p4;
            p4.x = f0.x * il16[ir];
            p4.y = f0.y * il16[ir];
            p4.z = f1.x * il16[ir];
            p4.w = f1.y * il16[ir];
            *(float4*)(sc + (size_t)row * S_ + k0 + tx * 4) = p4;  // prob out
            int c = tx >> 1;
            __half* pp = hP + row * 64 + ((c ^ (row & 7)) * 8) + (tx & 1) * 4;
            *(__half2*)(pp)     = __floats2half2_rn(p4.x, p4.y);
            *(__half2*)(pp + 2) = __floats2half2_rn(p4.z, p4.w);
        }
        __syncthreads();

        const uint32_t vb = hKb + buf * 8192;
#pragma unroll
        for (int kt = 0; kt < 4; kt++) {
            uint32_t pf[2][4], vf[2][2], t4[4];
#pragma unroll
            for (int i = 0; i < 2; i++) {
                int cc = ((kt << 1) | ls4) ^ (q_rr[i] & 7);
                ldmx4(pf[i], hPb + q_rr[i] * 128 + cc * 16);
            }
            {
                int rr = kt * 16 + lr8;
                int cc = v_cc_raw ^ (rr & 7);
                ldmx4t(t4, vb + rr * 128 + cc * 16);
                vf[0][0] = t4[0]; vf[0][1] = t4[1];
                vf[1][0] = t4[2]; vf[1][1] = t4[3];
            }
#pragma unroll
            for (int i = 0; i < 2; i++)
#pragma unroll
                for (int j = 0; j < 2; j++)
                    mma_f16(ctx[i][j], pf[i], vf[j]);
        }
    }

    // ---- store ctx (fp16) -------------------------------------------------
#pragma unroll
    for (int i = 0; i < 2; i++) {
        int r0 = q0 + warpM * 32 + i * 16 + g;
#pragma unroll
        for (int j = 0; j < 2; j++) {
            int cl = hI * 64 + warpN * 16 + j * 8 + tq * 2;
            *(__half2*)(g_ctxh + ((size_t)bI * S_ + r0) * HD_ + cl) =
                __floats2half2_rn(ctx[i][j][0], ctx[i][j][1]);
            *(__half2*)(g_ctxh + ((size_t)bI * S_ + r0 + 8) * HD_ + cl) =
                __floats2half2_rn(ctx[i][j][2], ctx[i][j][3]);
        }
    }
}

// ---------------- launcher ------------------------------------------------
extern "C" void kernel_launch(void* const* d_in, const int* in_sizes, int n_in,
                              void* d_out, int out_size) {
    const float* Q  = (const float*)d_in[0];
    const float* K  = (const float*)d_in[1];
    const float* V  = (const float*)d_in[2];
    const void*  mask = d_in[3];
    const float* WQ = (const float*)d_in[4];
    const float* bQ = (const float*)d_in[5];
    const float* WK = (const float*)d_in[6];
    const float* bK = (const float*)d_in[7];
    const float* WV = (const float*)d_in[8];
    const float* bV = (const float*)d_in[9];
    const float* WO = (const float*)d_in[10];
    const float* bO = (const float*)d_in[11];

    float* y    = (float*)d_out;
    float* prob = y + (size_t)N_ * E_;

    __half *ah, *wth, *ctxh;
    cudaGetSymbolAddress((void**)&ah,   g_ah3);
    cudaGetSymbolAddress((void**)&wth,  g_wth4);
    cudaGetSymbolAddress((void**)&ctxh, g_ctxh);

    cudaFuncSetAttribute(attn_kernel,
                         cudaFuncAttributeMaxDynamicSharedMemorySize, ATTN_SMEM);

    dim3 blk(256);
    dim3 gproj(HD_ / 128, N_ / 128);

    conv_a3_kernel<<<dim3(4096, 3), 256>>>(Q, K, V);
    conv_wt4_kernel<<<dim3(32, 32, 4), dim3(32, 8)>>>(WQ, WK, WV, WO);

    gemm_h_kernel<<<gproj, blk>>>(ah,                       wth,                        bQ, nullptr, 0);
    gemm_h_kernel<<<gproj, blk>>>(ah + (size_t)N_ * E_,     wth + (size_t)E_ * HD_,     bK, nullptr, 1);
    gemm_h_kernel<<<gproj, blk>>>(ah + (size_t)2 * N_ * E_, wth + (size_t)2 * E_ * HD_, bV, nullptr, 2);

    attn_kernel<<<dim3(S_ / 64, B_ * H_), blk, ATTN_SMEM>>>(mask, prob);

    gemm_h_kernel<<<gproj, blk>>>(ctxh, wth + (size_t)3 * E_ * HD_, bO, y, 3);
}

// round 12
// speedup vs baseline: 1.4143x; 1.1784x over previous
#include <cuda_runtime.h>
#include <cuda_fp16.h>
#include <cstdint>

// Problem constants
#define B_   2
#define S_   2048
#define E_   1024
#define H_   16
#define D_   64
#define HD_  1024
#define N_   4096            // B*S
#define SCALE_ 0.125f        // 1/sqrt(64), exact power of two
#define NEG_  -1e9f

// ---------------- scratch (device globals; no allocations allowed) -------
__device__ __half g_qh[(size_t)B_ * H_ * S_ * D_];   // [bh][s][d], pre-scaled
__device__ __half g_kh[(size_t)B_ * H_ * S_ * D_];
__device__ __half g_vh[(size_t)B_ * H_ * S_ * D_];
__device__ __half g_ctxh[(size_t)N_ * HD_];          // [b*S+s][h*D+d]
__device__ __half g_ah3[(size_t)3 * N_ * E_];        // staged Q/K/V inputs (fp16)
__device__ __half g_wth4[(size_t)4 * E_ * HD_];      // staged W^T x4 (fp16)
__device__ __half g_eh[(size_t)B_ * H_ * S_ * S_];   // exp-scores / 16 (fp16)

// ---------------- helpers --------------------------------------------------
__device__ __forceinline__ uint32_t cvta_smem(const void* p) {
    uint32_t a;
    asm("{ .reg .u64 t; cvta.to.shared.u64 t, %1; cvt.u32.u64 %0, t; }"
        : "=r"(a) : "l"(p));
    return a;
}
__device__ __forceinline__ void ldmx4(uint32_t* d, uint32_t a) {
    asm volatile("ldmatrix.sync.aligned.m8n8.x4.shared.b16 {%0,%1,%2,%3}, [%4];"
                 : "=r"(d[0]), "=r"(d[1]), "=r"(d[2]), "=r"(d[3]) : "r"(a));
}
__device__ __forceinline__ void ldmx4t(uint32_t* d, uint32_t a) {
    asm volatile("ldmatrix.sync.aligned.m8n8.x4.trans.shared.b16 {%0,%1,%2,%3}, [%4];"
                 : "=r"(d[0]), "=r"(d[1]), "=r"(d[2]), "=r"(d[3]) : "r"(a));
}
__device__ __forceinline__ void mma_f16(float* c, const uint32_t* a,
                                        const uint32_t* b) {
    asm volatile(
        "mma.sync.aligned.m16n8k16.row.col.f32.f16.f16.f32 "
        "{%0,%1,%2,%3}, {%4,%5,%6,%7}, {%8,%9}, {%0,%1,%2,%3};"
        : "+f"(c[0]), "+f"(c[1]), "+f"(c[2]), "+f"(c[3])
        : "r"(a[0]), "r"(a[1]), "r"(a[2]), "r"(a[3]), "r"(b[0]), "r"(b[1]));
}
__device__ __forceinline__ void cp16(uint32_t saddr, const void* gaddr) {
    asm volatile("cp.async.cg.shared.global [%0], [%1], 16;"
                 :: "r"(saddr), "l"(gaddr) : "memory");
}
#define CP_COMMIT() asm volatile("cp.async.commit_group;" ::: "memory")
#define CP_WAIT0()  asm volatile("cp.async.wait_group 0;" ::: "memory")

// ---------------- staging kernels ------------------------------------------
__global__ void conv_a3_kernel(const float* __restrict__ Q,
                               const float* __restrict__ K,
                               const float* __restrict__ V) {
    const float* src = (blockIdx.y == 0) ? Q : (blockIdx.y == 1) ? K : V;
    __half* out = g_ah3 + (size_t)blockIdx.y * N_ * E_;
    size_t i = ((size_t)blockIdx.x * 256 + threadIdx.x) * 4;
    float4 v = *(const float4*)(src + i);
    *(__half2*)(out + i)     = __floats2half2_rn(v.x, v.y);
    *(__half2*)(out + i + 2) = __floats2half2_rn(v.z, v.w);
}

__global__ void conv_wt4_kernel(const float* __restrict__ W0,
                                const float* __restrict__ W1,
                                const float* __restrict__ W2,
                                const float* __restrict__ W3) {
    __shared__ __half t[32][33];
    const float* W = (blockIdx.z == 0) ? W0 : (blockIdx.z == 1) ? W1
                   : (blockIdx.z == 2) ? W2 : W3;
    __half* WT = g_wth4 + (size_t)blockIdx.z * E_ * HD_;
    int n0 = blockIdx.x * 32, k0 = blockIdx.y * 32;
    int tx = threadIdx.x, ty = threadIdx.y;
#pragma unroll
    for (int i = 0; i < 4; i++)
        t[ty + i * 8][tx] = __float2half(W[(size_t)(k0 + ty + i * 8) * HD_ + n0 + tx]);
    __syncthreads();
#pragma unroll
    for (int i = 0; i < 4; i++)
        WT[(size_t)(n0 + ty + i * 8) * E_ + k0 + tx] = t[tx][ty + i * 8];
}

// ============ fp16 ldmatrix GEMM — 80B rows + cp.async loader ==============
#define RSTRIDE 40
#define TILEBUF (128 * RSTRIDE)

__global__ void __launch_bounds__(256) gemm_h_kernel(
    const __half* __restrict__ Ah, const __half* __restrict__ WT,
    const float* __restrict__ bias, float* __restrict__ outp, int sel) {

    __shared__ __half sA[2][TILEBUF];
    __shared__ __half sB[2][TILEBUF];

    const int tid = threadIdx.x;
    const int wid = tid >> 5, lane = tid & 31;
    const int m0 = blockIdx.y * 128, c0 = blockIdx.x * 128;
    const int warpM = wid & 1, warpN = wid >> 1;
    const int g = lane >> 2, tq = lane & 3;

    const uint32_t sAb0 = cvta_smem(sA[0]), sBb0 = cvta_smem(sB[0]);

    const int l_row = tid >> 2;
    const int l_c   = tid & 3;

    auto load_async = [&](int buf, int k0) {
#pragma unroll
        for (int e = 0; e < 2; e++) {
            int row = l_row + e * 64;
            cp16(sAb0 + buf * (TILEBUF * 2) + row * (RSTRIDE * 2) + l_c * 16,
                 Ah + (size_t)(m0 + row) * E_ + k0 + l_c * 8);
            cp16(sBb0 + buf * (TILEBUF * 2) + row * (RSTRIDE * 2) + l_c * 16,
                 WT + (size_t)(c0 + row) * E_ + k0 + l_c * 8);
        }
        CP_COMMIT();
    };

    const int lr8 = (lane & 7) + ((lane >> 3) & 1) * 8;
    const int ls4 = lane >> 4;
    int a_rr[4], b_rr[2];
#pragma unroll
    for (int i = 0; i < 4; i++) a_rr[i] = warpM * 64 + i * 16 + lr8;
#pragma unroll
    for (int j = 0; j < 2; j++) b_rr[j] = warpN * 32 + j * 16 + lr8;

    float c[4][4][4] = {};

    load_async(0, 0);

    for (int ch = 0; ch < 32; ch++) {
        const int buf = ch & 1;
        CP_WAIT0();
        __syncthreads();
        if (ch < 31) load_async(buf ^ 1, (ch + 1) * 32);

        const uint32_t ab = sAb0 + buf * (TILEBUF * 2);
        const uint32_t bb = sBb0 + buf * (TILEBUF * 2);
#pragma unroll
        for (int kt = 0; kt < 2; kt++) {
            const int cc = (kt << 1) | ls4;
            uint32_t af[4][4];
            uint32_t bf[4][2];
#pragma unroll
            for (int i = 0; i < 4; i++)
                ldmx4(af[i], ab + a_rr[i] * (RSTRIDE * 2) + cc * 16);
#pragma unroll
            for (int jj = 0; jj < 2; jj++) {
                uint32_t t4[4];
                ldmx4(t4, bb + b_rr[jj] * (RSTRIDE * 2) + cc * 16);
                bf[jj * 2][0] = t4[0]; bf[jj * 2 + 1][0] = t4[1];
                bf[jj * 2][1] = t4[2]; bf[jj * 2 + 1][1] = t4[3];
            }
#pragma unroll
            for (int i = 0; i < 4; i++)
#pragma unroll
                for (int j = 0; j < 4; j++)
                    mma_f16(c[i][j], af[i], bf[j]);
        }
    }

    const float osc = (sel == 0) ? SCALE_ : 1.0f;
    __half* hdst = (sel == 0) ? g_qh : (sel == 1) ? g_kh : g_vh;
#pragma unroll
    for (int i = 0; i < 4; i++) {
        int rtop = m0 + warpM * 64 + i * 16 + g;
        int rbot = rtop + 8;
#pragma unroll
        for (int j = 0; j < 4; j++) {
            int coln = c0 + warpN * 32 + j * 8 + tq * 2;
            float2 bb2 = *(const float2*)(bias + coln);
            float v00 = c[i][j][0] + bb2.x, v01 = c[i][j][1] + bb2.y;
            float v10 = c[i][j][2] + bb2.x, v11 = c[i][j][3] + bb2.y;
            if (sel < 3) {
                int hI = coln >> 6, dI = coln & 63;
                int b0I = rtop >> 11, s0I = rtop & (S_ - 1);
                int b1I = rbot >> 11, s1I = rbot & (S_ - 1);
                *(__half2*)(hdst + (((size_t)b0I * H_ + hI) * S_ + s0I) * D_ + dI) =
                    __floats2half2_rn(v00 * osc, v01 * osc);
                *(__half2*)(hdst + (((size_t)b1I * H_ + hI) * S_ + s1I) * D_ + dI) =
                    __floats2half2_rn(v10 * osc, v11 * osc);
            } else {
                *(float2*)(outp + (size_t)rtop * HD_ + coln) = make_float2(v00, v01);
                *(float2*)(outp + (size_t)rbot * HD_ + coln) = make_float2(v10, v11);
            }
        }
    }
}

// ---------------- attention --------------------------------------------------
// Pass 1: cp.async K; mma scores -> sS; mask+exp -> e/16 fp16 -> g_eh; per-lane
//         partial row sums (reduction deferred to after the loop).
// Pass 2: cp.async V AND e tiles; mma ctx += (e/16) @ V directly on staged e;
//         scalar reads e from smem -> prob fp32. ONE barrier/iter. ctx scaled
//         by 16/l at epilogue via smem sIl[64].
#define ATTN_SMEM (24576 + 17408 + 256)

__global__ void __launch_bounds__(256) attn_kernel(
    const void* __restrict__ mask, float* __restrict__ prob) {

    extern __shared__ char smraw[];
    __half* hQ  = (__half*)smraw;                 // 8 KB
    __half* hKV = hQ + 4096;                      // 2 x 8 KB (K pass1 / V pass2)
    float*  sS  = (float*)(smraw + 24576);        // 64x68 fp32 (pass1)
    __half* hE  = (__half*)sS;                    // pass2 alias: 2 x 8 KB e tiles
    float*  sIl = (float*)(smraw + 24576 + 17408);// 64 row scales

    const int tid = threadIdx.x, tx = tid & 15, ty = tid >> 4;
    const int wid = tid >> 5, lane = tid & 31;
    const int warpM = wid & 1, warpN = wid >> 1;
    const int g = lane >> 2, tq = lane & 3;
    const int bh = blockIdx.y, q0 = blockIdx.x * 64;
    const int bI = bh >> 4, hI = bh & 15;

    __shared__ int s_mm;
    {
        unsigned int v = ((const unsigned int*)mask)[tid];
        int isf = __syncthreads_or(v == 0x3F800000u);
        int big = __syncthreads_or(v > 1u);
        if (tid == 0) s_mm = isf ? 2 : (big ? 0 : 1);
    }

    const __half* qg = g_qh + (size_t)bh * S_ * D_ + (size_t)q0 * D_;
    const __half* kg = g_kh + (size_t)bh * S_ * D_;
    const __half* vg = g_vh + (size_t)bh * S_ * D_;
    float* sc = prob + ((size_t)bh * S_ + q0) * S_;
    __half* eg = g_eh + ((size_t)bh * S_ + q0) * S_;

    const uint32_t hQb = cvta_smem(hQ), hKVb = cvta_smem(hKV);
    const uint32_t hEb = cvta_smem(hE);

    const int tl_row = tid >> 2;
    {
#pragma unroll
        for (int e = 0; e < 2; e++) {
            int c = (tid & 3) * 2 + e;
            uint4 v = *(const uint4*)(qg + (size_t)tl_row * 64 + c * 8);
            *(uint4*)(hQ + tl_row * 64 + ((c ^ (tl_row & 7)) * 8)) = v;
        }
    }
    auto load_kv = [&](int buf, const __half* src, int k0) {
#pragma unroll
        for (int e = 0; e < 2; e++) {
            int c = (tid & 3) * 2 + e;
            cp16(hKVb + buf * 8192 + tl_row * 128 + ((c ^ (tl_row & 7)) * 16),
                 src + (size_t)(k0 + tl_row) * 64 + c * 8);
        }
    };
    auto load_e = [&](int buf, int k0) {
#pragma unroll
        for (int e = 0; e < 2; e++) {
            int c = (tid & 3) * 2 + e;
            cp16(hEb + buf * 8192 + tl_row * 128 + ((c ^ (tl_row & 7)) * 16),
                 eg + (size_t)tl_row * S_ + k0 + c * 8);
        }
    };

    const int lr8 = (lane & 7) + ((lane >> 3) & 1) * 8;
    const int ls4 = lane >> 4;
    int q_rr[2];
#pragma unroll
    for (int i = 0; i < 2; i++) q_rr[i] = warpM * 32 + i * 16 + lr8;
    const int k_rr = warpN * 16 + lr8;
    const int v_cc_raw = warpN * 2 + ls4;

    const int mm = s_mm;
    float l[4] = {0.f, 0.f, 0.f, 0.f};

    // =================== pass 1: exp-scores + partial sums ================
    load_kv(0, kg, 0);
    CP_COMMIT();
    for (int kt0 = 0; kt0 < 32; kt0++) {
        const int buf = kt0 & 1;
        CP_WAIT0();
        __syncthreads();
        if (kt0 < 31) { load_kv(buf ^ 1, kg, (kt0 + 1) * 64); CP_COMMIT(); }

        float cs[2][2][4] = {};
        const uint32_t kb = hKVb + buf * 8192;
#pragma unroll
        for (int kt = 0; kt < 4; kt++) {
            uint32_t af[2][4], bf[2][2], t4[4];
#pragma unroll
            for (int i = 0; i < 2; i++) {
                int cc = ((kt << 1) | ls4) ^ (q_rr[i] & 7);
                ldmx4(af[i], hQb + q_rr[i] * 128 + cc * 16);
            }
            {
                int cc = ((kt << 1) | ls4) ^ (k_rr & 7);
                ldmx4(t4, kb + k_rr * 128 + cc * 16);
                bf[0][0] = t4[0]; bf[1][0] = t4[1];
                bf[0][1] = t4[2]; bf[1][1] = t4[3];
            }
#pragma unroll
            for (int i = 0; i < 2; i++)
#pragma unroll
                for (int j = 0; j < 2; j++)
                    mma_f16(cs[i][j], af[i], bf[j]);
        }
#pragma unroll
        for (int i = 0; i < 2; i++) {
            int r0 = warpM * 32 + i * 16 + g;
#pragma unroll
            for (int j = 0; j < 2; j++) {
                int cl = warpN * 16 + j * 8 + tq * 2;
                *(float2*)(sS + r0 * 68 + cl)       = make_float2(cs[i][j][0], cs[i][j][1]);
                *(float2*)(sS + (r0 + 8) * 68 + cl) = make_float2(cs[i][j][2], cs[i][j][3]);
            }
        }
        __syncthreads();

        const int k0 = kt0 * 64;
#pragma unroll
        for (int ir = 0; ir < 4; ir++) {
            int row = ty * 4 + ir;
            float4 s4 = *(const float4*)(sS + row * 68 + tx * 4);
            float acc[4] = {s4.x, s4.y, s4.z, s4.w};
            size_t moff = ((size_t)bI * S_ + q0 + row) * S_ + k0 + tx * 4;
            if (mm == 0) {
                uchar4 u = *(const uchar4*)((const unsigned char*)mask + moff);
                if (u.x) acc[0] = NEG_;
                if (u.y) acc[1] = NEG_;
                if (u.z) acc[2] = NEG_;
                if (u.w) acc[3] = NEG_;
            } else if (mm == 1) {
                int4 u = *(const int4*)((const int*)mask + moff);
                if (u.x) acc[0] = NEG_;
                if (u.y) acc[1] = NEG_;
                if (u.z) acc[2] = NEG_;
                if (u.w) acc[3] = NEG_;
            } else {
                float4 u = *(const float4*)((const float*)mask + moff);
                if (u.x != 0.f) acc[0] = NEG_;
                if (u.y != 0.f) acc[1] = NEG_;
                if (u.z != 0.f) acc[2] = NEG_;
                if (u.w != 0.f) acc[3] = NEG_;
            }
            float4 e4;
            e4.x = __expf(acc[0]);
            e4.y = __expf(acc[1]);
            e4.z = __expf(acc[2]);
            e4.w = __expf(acc[3]);
            __half2 h0 = __floats2half2_rn(e4.x * 0.0625f, e4.y * 0.0625f);
            __half2 h1 = __floats2half2_rn(e4.z * 0.0625f, e4.w * 0.0625f);
            uint2 ev;
            ev.x = *(uint32_t*)&h0;
            ev.y = *(uint32_t*)&h1;
            *(uint2*)(eg + (size_t)row * S_ + k0 + tx * 4) = ev;
            l[ir] += e4.x + e4.y + e4.z + e4.w;   // per-lane partial
        }
    }

    // deferred row-sum reduction + publish 16/l
    float il16[4];
#pragma unroll
    for (int ir = 0; ir < 4; ir++) {
#pragma unroll
        for (int o = 8; o; o >>= 1)
            l[ir] += __shfl_xor_sync(0xffffffffu, l[ir], o);
        il16[ir] = 16.0f / l[ir];
        if (tx == 0) sIl[ty * 4 + ir] = il16[ir];
    }
    __syncthreads();   // sS last reads done; hE/V loads may begin

    // =================== pass 2: prob + ctx = (e/16) @ V ==================
    float ctx[2][2][4] = {};

    load_kv(0, vg, 0);
    load_e(0, 0);
    CP_COMMIT();
    for (int kt0 = 0; kt0 < 32; kt0++) {
        const int buf = kt0 & 1;
        CP_WAIT0();
        __syncthreads();
        if (kt0 < 31) {
            load_kv(buf ^ 1, vg, (kt0 + 1) * 64);
            load_e(buf ^ 1, (kt0 + 1) * 64);
            CP_COMMIT();
        }

        const int k0 = kt0 * 64;
        // scalar: prob = e * (16/l), read e from smem
#pragma unroll
        for (int ir = 0; ir < 4; ir++) {
            int row = ty * 4 + ir;
            const __half* ep = hE + buf * 4096 + row * 64 +
                               (((tx >> 1) ^ (row & 7)) * 8) + (tx & 1) * 4;
            uint2 ev = *(const uint2*)ep;
            float2 f0 = __half22float2(*(__half2*)&ev.x);
            float2 f1 = __half22float2(*(__half2*)&ev.y);
            float4 p4;
            p4.x = f0.x * il16[ir];
            p4.y = f0.y * il16[ir];
            p4.z = f1.x * il16[ir];
            p4.w = f1.y * il16[ir];
            *(float4*)(sc + (size_t)row * S_ + k0 + tx * 4) = p4;  // prob out
        }

        // mma: ctx += E(64x64) @ V(64x64)   (E = e/16 fp16, straight from stage)
        const uint32_t eb = hEb + buf * 8192;
        const uint32_t vb = hKVb + buf * 8192;
#pragma unroll
        for (int kt = 0; kt < 4; kt++) {
            uint32_t pf[2][4], vf[2][2], t4[4];
#pragma unroll
            for (int i = 0; i < 2; i++) {
                int cc = ((kt << 1) | ls4) ^ (q_rr[i] & 7);
                ldmx4(pf[i], eb + q_rr[i] * 128 + cc * 16);
            }
            {
                int rr = kt * 16 + lr8;
                int cc = v_cc_raw ^ (rr & 7);
                ldmx4t(t4, vb + rr * 128 + cc * 16);
                vf[0][0] = t4[0]; vf[0][1] = t4[1];
                vf[1][0] = t4[2]; vf[1][1] = t4[3];
            }
#pragma unroll
            for (int i = 0; i < 2; i++)
#pragma unroll
                for (int j = 0; j < 2; j++)
                    mma_f16(ctx[i][j], pf[i], vf[j]);
        }
    }

    // ---- store ctx (fp16), scaled by 16/l per row -------------------------
#pragma unroll
    for (int i = 0; i < 2; i++) {
        int lr0 = warpM * 32 + i * 16 + g;
        float s0 = sIl[lr0], s1 = sIl[lr0 + 8];
        int r0 = q0 + lr0;
#pragma unroll
        for (int j = 0; j < 2; j++) {
            int cl = hI * 64 + warpN * 16 + j * 8 + tq * 2;
            *(__half2*)(g_ctxh + ((size_t)bI * S_ + r0) * HD_ + cl) =
                __floats2half2_rn(ctx[i][j][0] * s0, ctx[i][j][1] * s0);
            *(__half2*)(g_ctxh + ((size_t)bI * S_ + r0 + 8) * HD_ + cl) =
                __floats2half2_rn(ctx[i][j][2] * s1, ctx[i][j][3] * s1);
        }
    }
}

// ---------------- launcher ------------------------------------------------
extern "C" void kernel_launch(void* const* d_in, const int* in_sizes, int n_in,
                              void* d_out, int out_size) {
    const float* Q  = (const float*)d_in[0];
    const float* K  = (const float*)d_in[1];
    const float* V  = (const float*)d_in[2];
    const void*  mask = d_in[3];
    const float* WQ = (const float*)d_in[4];
    const float* bQ = (const float*)d_in[5];
    const float* WK = (const float*)d_in[6];
    const float* bK = (const float*)d_in[7];
    const float* WV = (const float*)d_in[8];
    const float* bV = (const float*)d_in[9];
    const float* WO = (const float*)d_in[10];
    const float* bO = (const float*)d_in[11];

    float* y    = (float*)d_out;
    float* prob = y + (size_t)N_ * E_;

    __half *ah, *wth, *ctxh;
    cudaGetSymbolAddress((void**)&ah,   g_ah3);
    cudaGetSymbolAddress((void**)&wth,  g_wth4);
    cudaGetSymbolAddress((void**)&ctxh, g_ctxh);

    cudaFuncSetAttribute(attn_kernel,
                         cudaFuncAttributeMaxDynamicSharedMemorySize, ATTN_SMEM);

    dim3 blk(256);
    dim3 gproj(HD_ / 128, N_ / 128);

    conv_a3_kernel<<<dim3(4096, 3), 256>>>(Q, K, V);
    conv_wt4_kernel<<<dim3(32, 32, 4), dim3(32, 8)>>>(WQ, WK, WV, WO);

    gemm_h_kernel<<<gproj, blk>>>(ah,                       wth,                        bQ, nullptr, 0);
    gemm_h_kernel<<<gproj, blk>>>(ah + (size_t)N_ * E_,     wth + (size_t)E_ * HD_,     bK, nullptr, 1);
    gemm_h_kernel<<<gproj, blk>>>(ah + (size_t)2 * N_ * E_, wth + (size_t)2 * E_ * HD_, bV, nullptr, 2);

    attn_kernel<<<dim3(S_ / 64, B_ * H_), blk, ATTN_SMEM>>>(mask, prob);

    gemm_h_kernel<<<gproj, blk>>>(ctxh, wth + (size_t)3 * E_ * HD_, bO, y, 3);
}